// round 14
// baseline (speedup 1.0000x reference)
#include <cuda_runtime.h>
#include <math.h>

#define B_ 64
#define M_ 16384
#define W_ 128
#define H_ 8
#define TILE_M 128
#define TPAD 132              // 128 + 4 floats padding -> conflict-free row reads
#define EPS 1e-6f

// ---------- packed f32x2 helpers (Blackwell FFMA2, PTX-only) ----------
__device__ __forceinline__ unsigned long long pk2(float lo, float hi) {
    unsigned long long r;
    asm("mov.b64 %0, {%1,%2};" : "=l"(r) : "f"(lo), "f"(hi));
    return r;
}
__device__ __forceinline__ void unpk2(unsigned long long v, float& lo, float& hi) {
    asm("mov.b64 {%0,%1}, %2;" : "=f"(lo), "=f"(hi) : "l"(v));
}
__device__ __forceinline__ unsigned long long fma2_(unsigned long long a,
                                                    unsigned long long b,
                                                    unsigned long long c) {
    unsigned long long d;
    asm("fma.rn.f32x2 %0, %1, %2, %3;" : "=l"(d) : "l"(a), "l"(b), "l"(c));
    return d;
}

// =====================================================================
// Kernel 1: weighted cosine scores
//   out[b,h,m] = softplus(strength[b,h]) * <key, mem_row> /
//                (||mem_row|| * ||key|| + eps)
// One block = 128 memory rows of one batch. Memory tile staged in padded
// smem; each thread owns one row, 18 independent f32x2 accumulators
// (8 heads x 2 + norm x 2) -> no shuffles, no accumulator dep-chains.
// =====================================================================
__global__ __launch_bounds__(TILE_M, 3) void cw_score_kernel(
    const float* __restrict__ mem, const float* __restrict__ keys,
    const float* __restrict__ stren, float* __restrict__ out)
{
    extern __shared__ float tile[];          // TILE_M x TPAD floats (67.6 KB)
    __shared__ float skey[H_][W_];           // 4 KB
    __shared__ float sknorm[H_];
    __shared__ float sscale[H_];

    const int tid = threadIdx.x;
    const int b   = blockIdx.y;
    const int m0  = blockIdx.x * TILE_M;

    // ---- keys -> smem ----
    const float* kb = keys + (size_t)b * (H_ * W_);
    #pragma unroll
    for (int i = tid; i < H_ * W_; i += TILE_M)
        skey[i / W_][i % W_] = kb[i];
    __syncthreads();

    // ---- per-head key norm + softplus(strength) ----
    if (tid < H_) {
        float s = 0.f;
        #pragma unroll
        for (int w = 0; w < W_; w++) {
            float kv = skey[tid][w];
            s = fmaf(kv, kv, s);
        }
        sknorm[tid] = sqrtf(s);
        float x = stren[b * H_ + tid];
        sscale[tid] = fmaxf(x, 0.f) + log1pf(__expf(-fabsf(x)));
    }

    // ---- memory tile -> padded smem (coalesced float4) ----
    const float4* g = (const float4*)(mem + (size_t)b * M_ * W_ + (size_t)m0 * W_);
    #pragma unroll
    for (int i = 0; i < 32; i++) {           // 32 float4 per thread
        int fidx = i * TILE_M + tid;         // 0..4095 contiguous in gmem
        int row  = fidx >> 5;                // 32 float4 per row
        int c4   = fidx & 31;
        float4 v = g[fidx];
        *(float4*)&tile[row * TPAD + c4 * 4] = v;
    }
    __syncthreads();

    // ---- compute: thread tid owns row tid of the tile ----
    unsigned long long accA[H_ + 1], accB[H_ + 1];
    #pragma unroll
    for (int i = 0; i < H_ + 1; i++) { accA[i] = 0ull; accB[i] = 0ull; }

    const float* trow = &tile[tid * TPAD];
    #pragma unroll 8
    for (int k4 = 0; k4 < 32; k4++) {
        float4 m = *(const float4*)(trow + k4 * 4);
        unsigned long long m01 = pk2(m.x, m.y);
        unsigned long long m23 = pk2(m.z, m.w);
        accA[H_] = fma2_(m01, m01, accA[H_]);    // norm (sum of squares)
        accB[H_] = fma2_(m23, m23, accB[H_]);
        #pragma unroll
        for (int h = 0; h < H_; h++) {
            float4 kv = *(const float4*)&skey[h][k4 * 4];   // broadcast LDS
            accA[h] = fma2_(m01, pk2(kv.x, kv.y), accA[h]);
            accB[h] = fma2_(m23, pk2(kv.z, kv.w), accB[h]);
        }
    }

    float nlo, nhi, nlo2, nhi2;
    unpk2(accA[H_], nlo, nhi);
    unpk2(accB[H_], nlo2, nhi2);
    float nrm = sqrtf((nlo + nhi) + (nlo2 + nhi2));

    const int m = m0 + tid;
    #pragma unroll
    for (int h = 0; h < H_; h++) {
        float a, bq, c, d;
        unpk2(accA[h], a, bq);
        unpk2(accB[h], c, d);
        float score = (a + bq) + (c + d);
        float denom = fmaf(nrm, sknorm[h], EPS);
        out[((size_t)(b * H_ + h)) * M_ + m] = __fdividef(score * sscale[h], denom);
    }
}

// =====================================================================
// Kernel 2: in-place softmax over M for each (b,h).
// One block per (b,h); row (64 KB) stashed in smem so gmem is touched
// exactly once for read and once for write.
// =====================================================================
__global__ __launch_bounds__(256, 3) void cw_softmax_kernel(float* __restrict__ data)
{
    extern __shared__ float sbuf[];          // M_ floats (64 KB)
    __shared__ float red[8];

    const int tid = threadIdx.x;
    float* base = data + (size_t)blockIdx.x * M_;
    const float4* g4 = (const float4*)base;

    // ---- load + local max ----
    float lmax = __int_as_float(0xff800000); // -inf
    #pragma unroll
    for (int i = tid; i < M_ / 4; i += 256) {
        float4 v = g4[i];
        ((float4*)sbuf)[i] = v;
        lmax = fmaxf(lmax, fmaxf(fmaxf(v.x, v.y), fmaxf(v.z, v.w)));
    }
    #pragma unroll
    for (int o = 16; o > 0; o >>= 1)
        lmax = fmaxf(lmax, __shfl_xor_sync(0xffffffffu, lmax, o));
    if ((tid & 31) == 0) red[tid >> 5] = lmax;
    __syncthreads();
    float bmax = red[0];
    #pragma unroll
    for (int i = 1; i < 8; i++) bmax = fmaxf(bmax, red[i]);
    __syncthreads();                          // protect red reuse

    // ---- exp + local sum (exp kept in smem) ----
    float lsum = 0.f;
    #pragma unroll
    for (int i = tid; i < M_ / 4; i += 256) {
        float4 v = ((float4*)sbuf)[i];
        v.x = __expf(v.x - bmax);
        v.y = __expf(v.y - bmax);
        v.z = __expf(v.z - bmax);
        v.w = __expf(v.w - bmax);
        lsum += (v.x + v.y) + (v.z + v.w);
        ((float4*)sbuf)[i] = v;
    }
    #pragma unroll
    for (int o = 16; o > 0; o >>= 1)
        lsum += __shfl_xor_sync(0xffffffffu, lsum, o);
    if ((tid & 31) == 0) red[tid >> 5] = lsum;
    __syncthreads();
    float bsum = 0.f;
    #pragma unroll
    for (int i = 0; i < 8; i++) bsum += red[i];
    float inv = __fdividef(1.f, bsum);

    // ---- scale + write back ----
    float4* o4 = (float4*)base;
    #pragma unroll
    for (int i = tid; i < M_ / 4; i += 256) {
        float4 v = ((float4*)sbuf)[i];
        v.x *= inv; v.y *= inv; v.z *= inv; v.w *= inv;
        o4[i] = v;
    }
}

extern "C" void kernel_launch(void* const* d_in, const int* in_sizes, int n_in,
                              void* d_out, int out_size)
{
    const float* mem   = (const float*)d_in[0];   // [B, M, W]
    const float* keys  = (const float*)d_in[1];   // [B, H, W]
    const float* stren = (const float*)d_in[2];   // [B, H]
    float* out = (float*)d_out;                   // [B, H, M]

    // Opt-in smem > 48 KB (immediate API, not a graph node — capture-safe).
    cudaFuncSetAttribute(cw_score_kernel,
                         cudaFuncAttributeMaxDynamicSharedMemorySize,
                         TILE_M * TPAD * (int)sizeof(float));
    cudaFuncSetAttribute(cw_softmax_kernel,
                         cudaFuncAttributeMaxDynamicSharedMemorySize,
                         M_ * (int)sizeof(float));

    dim3 g1(M_ / TILE_M, B_);                     // (128, 64) blocks
    cw_score_kernel<<<g1, TILE_M, TILE_M * TPAD * sizeof(float)>>>(mem, keys, stren, out);
    cw_softmax_kernel<<<B_ * H_, 256, M_ * sizeof(float)>>>(out);
}

// round 15
// speedup vs baseline: 1.5982x; 1.5982x over previous
#include <cuda_runtime.h>
#include <math.h>
#include <stdint.h>

#define B_ 64
#define M_ 16384
#define W_ 128
#define H_ 8
#define ROWS 256              // memory rows per block (= threads per block)
#define CHW 32                // k-chunk width in floats (128 bytes per row)
#define NCH (W_ / CHW)        // 4 chunks
#define BUF_BYTES (ROWS * CHW * 4)   // 32 KB per stage
#define EPS 1e-6f

// ---------- packed f32x2 FMA (Blackwell FFMA2, PTX-only) ----------
__device__ __forceinline__ unsigned long long fma2_(unsigned long long a,
                                                    unsigned long long b,
                                                    unsigned long long c) {
    unsigned long long d;
    asm("fma.rn.f32x2 %0, %1, %2, %3;" : "=l"(d) : "l"(a), "l"(b), "l"(c));
    return d;
}
__device__ __forceinline__ void unpk2(unsigned long long v, float& lo, float& hi) {
    asm("mov.b64 {%0,%1}, %2;" : "=f"(lo), "=f"(hi) : "l"(v));
}
__device__ __forceinline__ void cpasync16(uint32_t saddr, const void* gaddr) {
    asm volatile("cp.async.cg.shared.global [%0], [%1], 16;\n"
                 :: "r"(saddr), "l"(gaddr));
}
__device__ __forceinline__ void cpasync_commit() {
    asm volatile("cp.async.commit_group;\n" ::: "memory");
}
__device__ __forceinline__ void cpasync_wait1() {
    asm volatile("cp.async.wait_group 1;\n" ::: "memory");
}

// =====================================================================
// Kernel 1: weighted cosine scores, cp.async double-buffered over k.
//   out[b,h,m] = softplus(strength) * <key,mem_row> / (|mem||key| + eps)
// Thread t owns memory row (m0 + t). Chunk buffers use a 16B-unit XOR
// swizzle (unit s of row r at s^(r&7)):
//   - cp.async write: quarter-warp = 1 row, s^(r&7) permutes segments
//   - LDS.128 read:  quarter-warp = 8 rows, r&7 permutes segments
// -> conflict-free in both directions with zero padding.
// =====================================================================
__global__ __launch_bounds__(ROWS, 3) void cw_score_kernel(
    const float* __restrict__ mem, const float* __restrict__ keys,
    const float* __restrict__ stren, float* __restrict__ out)
{
    extern __shared__ char sm[];                       // 2 x 32 KB stage buffers
    __shared__ __align__(16) float skey[H_][W_];       // 4 KB
    __shared__ float sknorm[H_];
    __shared__ float sscale[H_];

    const int tid = threadIdx.x;
    const int b   = blockIdx.y;
    const int m0  = blockIdx.x * ROWS;

    const uint32_t sm_u32 = (uint32_t)__cvta_generic_to_shared(sm);

    // per-thread cp.async geometry: thread t loads 16B unit s of rows r0+32j
    const int r0 = tid >> 3;
    const int s  = tid & 7;
    const uint32_t sw_st = (uint32_t)((s ^ (r0 & 7)) << 4);  // row&7 const over j
    const char* gsrc = (const char*)(mem + (size_t)b * M_ * W_ + (size_t)m0 * W_);

    // ---- prologue: start chunk 0 DMA immediately ----
    #pragma unroll
    for (int j = 0; j < 8; j++) {
        int row = r0 + 32 * j;
        cpasync16(sm_u32 + (uint32_t)(row * 128) + sw_st,
                  gsrc + (size_t)row * 512 + s * 16);
    }
    cpasync_commit();                                   // G0 = chunk 0

    // ---- keys -> smem (overlaps chunk-0 DMA) ----
    const float* kb = keys + (size_t)b * (H_ * W_);
    #pragma unroll
    for (int i = tid; i < H_ * W_; i += ROWS)
        skey[i >> 7][i & 127] = kb[i];
    __syncthreads();

    // ---- per-head key norm + softplus(strength) ----
    if (tid < H_) {
        float acc = 0.f;
        #pragma unroll
        for (int w = 0; w < W_; w++) {
            float kv = skey[tid][w];
            acc = fmaf(kv, kv, acc);
        }
        sknorm[tid] = sqrtf(acc);
        float x = stren[b * H_ + tid];
        sscale[tid] = fmaxf(x, 0.f) + log1pf(__expf(-fabsf(x)));
    }

    // ---- pipelined mainloop over 4 k-chunks ----
    unsigned long long accA[H_ + 1], accB[H_ + 1];
    #pragma unroll
    for (int i = 0; i < H_ + 1; i++) { accA[i] = 0ull; accB[i] = 0ull; }

    const uint32_t sw_ld = (uint32_t)((tid & 7) << 4);  // read-side XOR

    for (int c = 0; c < NCH; c++) {
        // issue chunk c+1 into the other buffer (empty group on last iter
        // keeps wait_group accounting uniform)
        if (c + 1 < NCH) {
            uint32_t dst = sm_u32 + (uint32_t)(((c + 1) & 1) * BUF_BYTES);
            const char* g = gsrc + (size_t)(c + 1) * 128;
            #pragma unroll
            for (int j = 0; j < 8; j++) {
                int row = r0 + 32 * j;
                cpasync16(dst + (uint32_t)(row * 128) + sw_st,
                          g + (size_t)row * 512 + s * 16);
            }
        }
        cpasync_commit();
        cpasync_wait1();                // chunk c resident (c+1 in flight)
        __syncthreads();                // all threads' DMAs visible

        const char* buf = sm + (c & 1) * BUF_BYTES + tid * 128;
        const float* kc = &skey[0][0] + c * CHW;        // skey[h] = kc + h*W_
        #pragma unroll
        for (int k4 = 0; k4 < 8; k4++) {
            ulonglong2 mm = *(const ulonglong2*)(buf + (((uint32_t)(k4 << 4)) ^ sw_ld));
            accA[H_] = fma2_(mm.x, mm.x, accA[H_]);     // self-dot (norm)
            accB[H_] = fma2_(mm.y, mm.y, accB[H_]);
            #pragma unroll
            for (int h = 0; h < H_; h++) {
                ulonglong2 kk = *(const ulonglong2*)(kc + h * W_ + k4 * 4); // broadcast
                accA[h] = fma2_(mm.x, kk.x, accA[h]);
                accB[h] = fma2_(mm.y, kk.y, accB[h]);
            }
        }
        __syncthreads();                // protect buffer before next DMA wave
    }

    // ---- epilogue ----
    float a0, a1, b0, b1;
    unpk2(accA[H_], a0, a1);
    unpk2(accB[H_], b0, b1);
    float nrm = sqrtf((a0 + a1) + (b0 + b1));

    const int m = m0 + tid;
    #pragma unroll
    for (int h = 0; h < H_; h++) {
        unpk2(accA[h], a0, a1);
        unpk2(accB[h], b0, b1);
        float score = (a0 + a1) + (b0 + b1);
        float denom = fmaf(nrm, sknorm[h], EPS);
        out[((size_t)(b * H_ + h)) * M_ + m] = __fdividef(score * sscale[h], denom);
    }
}

// =====================================================================
// Kernel 2: in-place softmax over M for each (b,h). Row stashed in smem
// so gmem is touched exactly once for read and once for write.
// =====================================================================
__global__ __launch_bounds__(256, 3) void cw_softmax_kernel(float* __restrict__ data)
{
    extern __shared__ float sbuf[];          // M_ floats (64 KB)
    __shared__ float red[8];

    const int tid = threadIdx.x;
    float* base = data + (size_t)blockIdx.x * M_;
    const float4* g4 = (const float4*)base;

    float lmax = __int_as_float(0xff800000); // -inf
    #pragma unroll 4
    for (int i = tid; i < M_ / 4; i += 256) {
        float4 v = g4[i];
        ((float4*)sbuf)[i] = v;
        lmax = fmaxf(lmax, fmaxf(fmaxf(v.x, v.y), fmaxf(v.z, v.w)));
    }
    #pragma unroll
    for (int o = 16; o > 0; o >>= 1)
        lmax = fmaxf(lmax, __shfl_xor_sync(0xffffffffu, lmax, o));
    if ((tid & 31) == 0) red[tid >> 5] = lmax;
    __syncthreads();
    float bmax = red[0];
    #pragma unroll
    for (int i = 1; i < 8; i++) bmax = fmaxf(bmax, red[i]);
    __syncthreads();

    float lsum = 0.f;
    #pragma unroll 4
    for (int i = tid; i < M_ / 4; i += 256) {
        float4 v = ((float4*)sbuf)[i];
        v.x = __expf(v.x - bmax);
        v.y = __expf(v.y - bmax);
        v.z = __expf(v.z - bmax);
        v.w = __expf(v.w - bmax);
        lsum += (v.x + v.y) + (v.z + v.w);
        ((float4*)sbuf)[i] = v;
    }
    #pragma unroll
    for (int o = 16; o > 0; o >>= 1)
        lsum += __shfl_xor_sync(0xffffffffu, lsum, o);
    if ((tid & 31) == 0) red[tid >> 5] = lsum;
    __syncthreads();
    float bsum = 0.f;
    #pragma unroll
    for (int i = 0; i < 8; i++) bsum += red[i];
    float inv = __fdividef(1.f, bsum);

    float4* o4 = (float4*)base;
    #pragma unroll 4
    for (int i = tid; i < M_ / 4; i += 256) {
        float4 v = ((float4*)sbuf)[i];
        v.x *= inv; v.y *= inv; v.z *= inv; v.w *= inv;
        o4[i] = v;
    }
}

extern "C" void kernel_launch(void* const* d_in, const int* in_sizes, int n_in,
                              void* d_out, int out_size)
{
    const float* mem   = (const float*)d_in[0];   // [B, M, W]
    const float* keys  = (const float*)d_in[1];   // [B, H, W]
    const float* stren = (const float*)d_in[2];   // [B, H]
    float* out = (float*)d_out;                   // [B, H, M]

    cudaFuncSetAttribute(cw_score_kernel,
                         cudaFuncAttributeMaxDynamicSharedMemorySize,
                         2 * BUF_BYTES);
    cudaFuncSetAttribute(cw_softmax_kernel,
                         cudaFuncAttributeMaxDynamicSharedMemorySize,
                         M_ * (int)sizeof(float));

    dim3 g1(M_ / ROWS, B_);                       // (64, 64) blocks
    cw_score_kernel<<<g1, ROWS, 2 * BUF_BYTES>>>(mem, keys, stren, out);
    cw_softmax_kernel<<<B_ * H_, 256, M_ * sizeof(float)>>>(out);
}